// round 4
// baseline (speedup 1.0000x reference)
#include <cuda_runtime.h>
#include <math.h>

#define B_   16
#define L_   1024
#define H_   8
#define E_   64
#define D_   512
#define LF   513
#define NROW 8192            // B_*D_

// ---------------- device scratch (no cudaMalloc allowed) -------------------
__device__ float  g_q2t[B_ * D_ * L_];
__device__ float  g_qf_re[NROW * LF];
__device__ float  g_qf_im[NROW * LF];
__device__ float  g_kf_re[NROW * LF];
__device__ float  g_kf_im[NROW * LF];
__device__ float  g_vf_re[NROW * LF];
__device__ float  g_vf_im[NROW * LF];
__device__ float  g_of_re[NROW * LF];
__device__ float  g_of_im[NROW * LF];
__device__ float2 g_tw[512];

// ---------------- packed f32x2 helpers ------------------------------------
__device__ __forceinline__ unsigned long long pk2(float lo, float hi) {
    unsigned long long r;
    asm("mov.b64 %0, {%1, %2};" : "=l"(r) : "f"(lo), "f"(hi));
    return r;
}
__device__ __forceinline__ void upk2(unsigned long long v, float& lo, float& hi) {
    asm("mov.b64 {%0, %1}, %2;" : "=f"(lo), "=f"(hi) : "l"(v));
}
__device__ __forceinline__ unsigned long long ffma2(unsigned long long a,
                                                    unsigned long long b,
                                                    unsigned long long c) {
    unsigned long long d;
    asm("fma.rn.f32x2 %0, %1, %2, %3;" : "=l"(d) : "l"(a), "l"(b), "l"(c));
    return d;
}
__device__ __forceinline__ unsigned long long neg2(unsigned long long a) {
    return a ^ 0x8000000080000000ULL;
}
__device__ __forceinline__ float sigmoidf_(float x) {
    return 1.0f / (1.0f + __expf(-x));
}

// row pitch 66 floats (even -> 8B-aligned LDS.64)
__device__ __forceinline__ int rowbase(int r) { return r * 66; }

// ---------------- twiddle table: exp(+2*pi*i*j/1024) -----------------------
__global__ void twiddle_kernel() {
    int j = threadIdx.x;
    if (j < 512) {
        float s, c;
        sincosf(6.283185307179586f * (float)j * (1.0f / 1024.0f), &s, &c);
        g_tw[j] = make_float2(c, s);
    }
}

// ---------------- Conv1d(512->1024,k=3,p=1) + GLU -> g_q2t[b,c,l] ----------
__global__ __launch_bounds__(256) void conv_glu_kernel(
        const float* __restrict__ q, const float* __restrict__ W,
        const float* __restrict__ bias) {
    __shared__ __align__(16) float pool[7200];
    float* sx  = pool;               // [16 ic][66 l]
    float* swa = pool + 1056;        // [48 r][64 oc]  r = ic*3+kw
    float* swg = pool + 1056 + 3072;

    int b   = blockIdx.x >> 4;
    int l0  = (blockIdx.x & 15) << 6;
    int oc0 = blockIdx.y << 6;
    int tid = threadIdx.x;
    int tx  = tid & 15, ty = tid >> 4;

    unsigned long long pa[4][2], pg[4][2];
#pragma unroll
    for (int i = 0; i < 4; i++) {
        pa[i][0] = pa[i][1] = 0ull;
        pg[i][0] = pg[i][1] = 0ull;
    }

    for (int ic0 = 0; ic0 < 512; ic0 += 16) {
        __syncthreads();
#pragma unroll
        for (int t = 0; t < 5; t++) {
            int idx = tid + (t << 8);
            if (idx < 1056) {
                int li = idx >> 4, kk = idx & 15;
                int l = l0 - 1 + li;
                float v = 0.0f;
                if ((unsigned)l < 1024u)
                    v = q[((size_t)b * 1024 + l) * 512 + ic0 + kk];
                sx[kk * 66 + li] = v;
            }
        }
#pragma unroll
        for (int t = 0; t < 12; t++) {
            int idx = tid + (t << 8);
            int oc = idx / 48, r = idx % 48;
            swa[r * 64 + oc] = W[(size_t)(oc0 + oc) * 1536 + ic0 * 3 + r];
        }
#pragma unroll
        for (int t = 0; t < 12; t++) {
            int idx = tid + (t << 8);
            int oc = idx / 48, r = idx % 48;
            swg[r * 64 + oc] = W[(size_t)(512 + oc0 + oc) * 1536 + ic0 * 3 + r];
        }
        __syncthreads();

#pragma unroll
        for (int kk = 0; kk < 16; kk++) {
            unsigned long long xm[4], x0[4], xp[4];
#pragma unroll
            for (int yl = 0; yl < 4; yl++) {
                int li = (ty << 2) + yl;
                float a  = sx[kk * 66 + li];
                float b2 = sx[kk * 66 + li + 1];
                float c2 = sx[kk * 66 + li + 2];
                xm[yl] = pk2(a, a); x0[yl] = pk2(b2, b2); xp[yl] = pk2(c2, c2);
            }
#pragma unroll
            for (int xl2 = 0; xl2 < 2; xl2++) {
                int oc = (tx << 2) + (xl2 << 1);
                unsigned long long wa0 = *(const unsigned long long*)(swa + (kk * 3 + 0) * 64 + oc);
                unsigned long long wa1 = *(const unsigned long long*)(swa + (kk * 3 + 1) * 64 + oc);
                unsigned long long wa2 = *(const unsigned long long*)(swa + (kk * 3 + 2) * 64 + oc);
                unsigned long long wg0 = *(const unsigned long long*)(swg + (kk * 3 + 0) * 64 + oc);
                unsigned long long wg1 = *(const unsigned long long*)(swg + (kk * 3 + 1) * 64 + oc);
                unsigned long long wg2 = *(const unsigned long long*)(swg + (kk * 3 + 2) * 64 + oc);
#pragma unroll
                for (int yl = 0; yl < 4; yl++) {
                    pa[yl][xl2] = ffma2(xm[yl], wa0, pa[yl][xl2]);
                    pa[yl][xl2] = ffma2(x0[yl], wa1, pa[yl][xl2]);
                    pa[yl][xl2] = ffma2(xp[yl], wa2, pa[yl][xl2]);
                    pg[yl][xl2] = ffma2(xm[yl], wg0, pg[yl][xl2]);
                    pg[yl][xl2] = ffma2(x0[yl], wg1, pg[yl][xl2]);
                    pg[yl][xl2] = ffma2(xp[yl], wg2, pg[yl][xl2]);
                }
            }
        }
    }

    __syncthreads();
    float* st = pool;                // [64 oc][65 l]
#pragma unroll
    for (int yl = 0; yl < 4; yl++) {
#pragma unroll
        for (int xl2 = 0; xl2 < 2; xl2++) {
            float a0, a1, g0, g1;
            upk2(pa[yl][xl2], a0, a1);
            upk2(pg[yl][xl2], g0, g1);
            int oc = (tx << 2) + (xl2 << 1);
            a0 += bias[oc0 + oc];       a1 += bias[oc0 + oc + 1];
            g0 += bias[512 + oc0 + oc]; g1 += bias[512 + oc0 + oc + 1];
            int li = (ty << 2) + yl;
            st[oc * 65 + li]       = a0 * sigmoidf_(g0);
            st[(oc + 1) * 65 + li] = a1 * sigmoidf_(g1);
        }
    }
    __syncthreads();
#pragma unroll
    for (int t = 0; t < 16; t++) {
        int idx = tid + (t << 8);
        int c = idx >> 6, li = idx & 63;
        g_q2t[((size_t)b * 512 + oc0 + c) * 1024 + l0 + li] = st[c * 65 + li];
    }
}

// ---------------- 1024-pt radix-2 Stockham (DIF, natural order) ------------
__device__ __forceinline__ void fft1024_shared(float2* bufA, float2* bufB,
                                               float sgn, int tid) {
    float2* src = bufA;
    float2* dst = bufB;
    int m = 1;
#pragma unroll
    for (int stage = 0; stage < 10; stage++) {
#pragma unroll
        for (int u = 0; u < 2; u++) {
            int idx = tid + (u << 8);
            float2 c0 = src[idx];
            float2 c1 = src[idx + 512];
            int k = idx & (m - 1);
            int o = idx + (idx - k);
            float2 w = g_tw[idx - k];
            float wy = w.y * sgn;
            float trx = c0.x - c1.x, trY = c0.y - c1.y;
            dst[o]     = make_float2(c0.x + c1.x, c0.y + c1.y);
            dst[o + m] = make_float2(w.x * trx - wy * trY, w.x * trY + wy * trx);
        }
        __syncthreads();
        float2* t = src; src = dst; dst = t;
        m <<= 1;
    }
}

// which: 0 = q (g_q2t contiguous), 1 = k, 2 = v ([B,S,H,E] strided)
__global__ __launch_bounds__(256) void rfft_kernel(const float* __restrict__ in,
                                                   int which) {
    __shared__ float2 bufA[1024];
    __shared__ float2 bufB[1024];
    int row = blockIdx.x, tid = threadIdx.x;
    if (which == 0) {
        const float* p = g_q2t + (size_t)row * 1024;
        for (int i = tid; i < 1024; i += 256) bufA[i] = make_float2(p[i], 0.0f);
    } else {
        const float* p = in + (size_t)(row >> 9) * 524288 + (row & 511);
        for (int i = tid; i < 1024; i += 256)
            bufA[i] = make_float2(p[(size_t)i * 512], 0.0f);
    }
    __syncthreads();
    fft1024_shared(bufA, bufB, -1.0f, tid);
    float* ore = (which == 0) ? g_qf_re : (which == 1) ? g_kf_re : g_vf_re;
    float* oim = (which == 0) ? g_qf_im : (which == 1) ? g_kf_im : g_vf_im;
    for (int i = tid; i < 513; i += 256) {
        float2 vv = bufA[i];
        ore[(size_t)row * 513 + i] = vv.x * 0.03125f;
        oim[(size_t)row * 513 + i] = vv.y * 0.03125f;
    }
}

// ---------------- fused frequency attention, f32x2 + conflict-free smem ----
// y-side micro-tile rows strided: row(j) = tx + 16*j  ->  LDS.64 bank-group
// (row*33 + off/2) mod 16 = (tx + e2) mod 16 : 16 distinct, conflict-free.
__global__ __launch_bounds__(256) void attn_kernel() {
    extern __shared__ float sm[];
    float* Qre = sm;                  // [x][e]
    float* Qim = sm + 4224;
    float* Ure = sm + 8448;           // K: [y][e]; later V: [e][y]
    float* Uim = sm + 12672;
    float* Tre = sm + 16896;          // [x][y]
    float* Tim = sm + 21120;

    int bh  = blockIdx.y;
    int x0  = blockIdx.x << 6;
    int tid = threadIdx.x;
    int tx  = tid & 15, ty = tid >> 4;
    size_t base = (size_t)bh * 64 * 513;

    // Q tile: gmem [e][x] -> smem [x][e]
#pragma unroll
    for (int t = 0; t < 16; t++) {
        int idx = tid + (t << 8);
        int e = idx >> 6, xi = idx & 63;
        int x = x0 + xi;
        float vr = 0.0f, vi = 0.0f;
        if (x < 513) {
            vr = g_qf_re[base + (size_t)e * 513 + x];
            vi = g_qf_im[base + (size_t)e * 513 + x];
        }
        int a = rowbase(xi) + e;
        Qre[a] = vr;
        Qim[a] = vi;
    }

    // micro-tile row bases: x-side contiguous (ty), y-side strided (tx + 16j)
    int qb[4], kb[4];
#pragma unroll
    for (int i = 0; i < 4; i++) qb[i] = rowbase((ty << 2) + i);
#pragma unroll
    for (int j = 0; j < 4; j++) kb[j] = rowbase(tx + (j << 4));

    unsigned long long ore_p[4][4], oim_p[4][4];
#pragma unroll
    for (int i = 0; i < 4; i++)
#pragma unroll
        for (int j = 0; j < 4; j++) { ore_p[i][j] = 0ull; oim_p[i][j] = 0ull; }
    float Dacc[4] = {};

    for (int yt = 0; yt < 9; yt++) {
        int y0 = yt << 6;
        __syncthreads();
        // K tile: gmem [e][y] -> smem [y][e]
#pragma unroll
        for (int t = 0; t < 16; t++) {
            int idx = tid + (t << 8);
            int e = idx >> 6, yi = idx & 63;
            int y = y0 + yi;
            float vr = 0.0f, vi = 0.0f;
            if (y < 513) {
                vr = g_kf_re[base + (size_t)e * 513 + y];
                vi = g_kf_im[base + (size_t)e * 513 + y];
            }
            int a = rowbase(yi) + e;
            Ure[a] = vr;
            Uim[a] = vi;
        }
        __syncthreads();

        // GEMM1: s[x,y] = sum_e qf*conj(kf), packed over e-pairs
        unsigned long long sre_p[4][4], sim_p[4][4];
#pragma unroll
        for (int i = 0; i < 4; i++)
#pragma unroll
            for (int j = 0; j < 4; j++) { sre_p[i][j] = 0ull; sim_p[i][j] = 0ull; }

        for (int e2 = 0; e2 < 32; e2++) {
            unsigned long long qr[4], qi[4], qrn[4], kr[4], ki[4];
            int off = e2 << 1;
#pragma unroll
            for (int i = 0; i < 4; i++) {
                qr[i] = *(const unsigned long long*)(Qre + qb[i] + off);
                qi[i] = *(const unsigned long long*)(Qim + qb[i] + off);
                qrn[i] = neg2(qr[i]);
            }
#pragma unroll
            for (int j = 0; j < 4; j++) {
                kr[j] = *(const unsigned long long*)(Ure + kb[j] + off);
                ki[j] = *(const unsigned long long*)(Uim + kb[j] + off);
            }
#pragma unroll
            for (int i = 0; i < 4; i++)
#pragma unroll
                for (int j = 0; j < 4; j++) {
                    sre_p[i][j] = ffma2(qr[i],  kr[j], sre_p[i][j]);
                    sre_p[i][j] = ffma2(qi[i],  ki[j], sre_p[i][j]);
                    sim_p[i][j] = ffma2(qi[i],  kr[j], sim_p[i][j]);
                    sim_p[i][j] = ffma2(qrn[i], ki[j], sim_p[i][j]);
                }
        }
        __syncthreads();   // K reads done; U about to become V

        // gating epilogue -> T[x][y] (y-col = tx + 16j) + D partials
#pragma unroll
        for (int i = 0; i < 4; i++)
#pragma unroll
            for (int j = 0; j < 4; j++) {
                float a0, a1, b0, b1;
                upk2(sre_p[i][j], a0, a1);
                upk2(sim_p[i][j], b0, b1);
                float sr = (a0 + a1) * 0.125f;
                float si = (b0 + b1) * 0.125f;
                float mg = sqrtf(sr * sr + si * si);
                float w  = 1.0f + sigmoidf_(mg);
                Dacc[i] += mg * w;
                int a = qb[i] + tx + (j << 4);
                Tre[a] = sr * w;
                Tim[a] = si * w;
            }
        // V tile: gmem [e][y] -> smem [e][y]
#pragma unroll
        for (int t = 0; t < 16; t++) {
            int idx = tid + (t << 8);
            int e = idx >> 6, yi = idx & 63;
            int y = y0 + yi;
            float vr = 0.0f, vi = 0.0f;
            if (y < 513) {
                vr = g_vf_re[base + (size_t)e * 513 + y];
                vi = g_vf_im[base + (size_t)e * 513 + y];
            }
            int a = rowbase(e) + yi;
            Ure[a] = vr;
            Uim[a] = vi;
        }
        __syncthreads();

        // GEMM2: of[x,e] += sum_y T[x,y]*V[e,y], packed over y-pairs
        for (int y2 = 0; y2 < 32; y2++) {
            unsigned long long tr[4], ti[4], tin[4], vr[4], vi[4];
            int off = y2 << 1;
#pragma unroll
            for (int i = 0; i < 4; i++) {
                tr[i] = *(const unsigned long long*)(Tre + qb[i] + off);
                ti[i] = *(const unsigned long long*)(Tim + qb[i] + off);
                tin[i] = neg2(ti[i]);
            }
#pragma unroll
            for (int j = 0; j < 4; j++) {
                vr[j] = *(const unsigned long long*)(Ure + kb[j] + off);
                vi[j] = *(const unsigned long long*)(Uim + kb[j] + off);
            }
#pragma unroll
            for (int i = 0; i < 4; i++)
#pragma unroll
                for (int j = 0; j < 4; j++) {
                    ore_p[i][j] = ffma2(tr[i],  vr[j], ore_p[i][j]);
                    ore_p[i][j] = ffma2(tin[i], vi[j], ore_p[i][j]);
                    oim_p[i][j] = ffma2(tr[i],  vi[j], oim_p[i][j]);
                    oim_p[i][j] = ffma2(ti[i],  vr[j], oim_p[i][j]);
                }
        }
    }

    // reduce D over tx lanes (bits 0..3)
#pragma unroll
    for (int i = 0; i < 4; i++) {
        float dsum = Dacc[i];
        dsum += __shfl_xor_sync(0xffffffffu, dsum, 1);
        dsum += __shfl_xor_sync(0xffffffffu, dsum, 2);
        dsum += __shfl_xor_sync(0xffffffffu, dsum, 4);
        dsum += __shfl_xor_sync(0xffffffffu, dsum, 8);
        Dacc[i] = 1.0f / fmaxf(dsum, 1e-12f);
    }
#pragma unroll
    for (int i = 0; i < 4; i++) {
        int x = x0 + (ty << 2) + i;
        if (x < 513) {
#pragma unroll
            for (int j = 0; j < 4; j++) {
                int e = tx + (j << 4);
                float a0, a1, b0, b1;
                upk2(ore_p[i][j], a0, a1);
                upk2(oim_p[i][j], b0, b1);
                g_of_re[base + (size_t)e * 513 + x] = (a0 + a1) * Dacc[i];
                g_of_im[base + (size_t)e * 513 + x] = (b0 + b1) * Dacc[i];
            }
        }
    }
}

// ---------------- irfft (ortho) + scatter to out[b,l,h,e] ------------------
__global__ __launch_bounds__(256) void irfft_kernel(float* __restrict__ out) {
    __shared__ float2 bufA[1024];
    __shared__ float2 bufB[1024];
    int row = blockIdx.x, tid = threadIdx.x;
    const float* pr = g_of_re + (size_t)row * 513;
    const float* pi = g_of_im + (size_t)row * 513;
    for (int i = tid; i < 1024; i += 256) {
        float re, im;
        if (i < 513) { re = pr[i];        im =  pi[i]; }
        else         { re = pr[1024 - i]; im = -pi[1024 - i]; }
        bufA[i] = make_float2(re, im);
    }
    __syncthreads();
    fft1024_shared(bufA, bufB, 1.0f, tid);
    int b = row >> 9, c = row & 511;
    float* po = out + (size_t)b * 524288 + c;
    for (int i = tid; i < 1024; i += 256)
        po[(size_t)i * 512] = bufA[i].x * 0.03125f;
}

// ---------------- launch ---------------------------------------------------
extern "C" void kernel_launch(void* const* d_in, const int* in_sizes, int n_in,
                              void* d_out, int out_size) {
    const float* q    = (const float*)d_in[0];
    const float* k    = (const float*)d_in[1];
    const float* v    = (const float*)d_in[2];
    const float* W    = (const float*)d_in[3];
    const float* bias = (const float*)d_in[4];
    float* out = (float*)d_out;

    const int attn_smem = 25344 * (int)sizeof(float);   // 101376 B
    cudaFuncSetAttribute(attn_kernel,
                         cudaFuncAttributeMaxDynamicSharedMemorySize, attn_smem);

    twiddle_kernel<<<1, 512>>>();
    conv_glu_kernel<<<dim3(256, 8), 256>>>(q, W, bias);
    rfft_kernel<<<NROW, 256>>>(nullptr, 0);
    rfft_kernel<<<NROW, 256>>>(k, 1);
    rfft_kernel<<<NROW, 256>>>(v, 2);
    attn_kernel<<<dim3(9, 128), 256, attn_smem>>>();
    irfft_kernel<<<NROW, 256>>>(out);
}

// round 5
// speedup vs baseline: 1.0133x; 1.0133x over previous
#include <cuda_runtime.h>
#include <math.h>

#define B_   16
#define L_   1024
#define H_   8
#define E_   64
#define D_   512
#define LF   513
#define NROW 8192            // B_*D_
#define VPITCH 514

// ---------------- device scratch (no cudaMalloc allowed) -------------------
__device__ float  g_q2t[B_ * D_ * L_];
// transposed spectra: [bh][x][e], contiguous in e (8B-aligned rows of 64)
__device__ __align__(16) float g_qft_re[128 * LF * 64];
__device__ __align__(16) float g_qft_im[128 * LF * 64];
__device__ __align__(16) float g_kft_re[128 * LF * 64];
__device__ __align__(16) float g_kft_im[128 * LF * 64];
// v spectra: [row=bh*64+e][y], padded pitch 514 for 8B alignment
__device__ __align__(16) float g_vf_re[NROW * VPITCH];
__device__ __align__(16) float g_vf_im[NROW * VPITCH];
__device__ float  g_of_re[NROW * LF];
__device__ float  g_of_im[NROW * LF];
__device__ float2 g_tw[512];

// ---------------- packed f32x2 helpers ------------------------------------
__device__ __forceinline__ unsigned long long pk2(float lo, float hi) {
    unsigned long long r;
    asm("mov.b64 %0, {%1, %2};" : "=l"(r) : "f"(lo), "f"(hi));
    return r;
}
__device__ __forceinline__ void upk2(unsigned long long v, float& lo, float& hi) {
    asm("mov.b64 {%0, %1}, %2;" : "=f"(lo), "=f"(hi) : "l"(v));
}
__device__ __forceinline__ unsigned long long ffma2(unsigned long long a,
                                                    unsigned long long b,
                                                    unsigned long long c) {
    unsigned long long d;
    asm("fma.rn.f32x2 %0, %1, %2, %3;" : "=l"(d) : "l"(a), "l"(b), "l"(c));
    return d;
}
__device__ __forceinline__ unsigned long long neg2(unsigned long long a) {
    return a ^ 0x8000000080000000ULL;
}
__device__ __forceinline__ float sigmoidf_(float x) {
    return 1.0f / (1.0f + __expf(-x));
}
__device__ __forceinline__ int rowbase(int r) { return r * 66; }

// cp.async 8B with zero-fill (srcsize in {0,4,8})
__device__ __forceinline__ void cp8(unsigned int dst, const void* src, int srcsize) {
    asm volatile("cp.async.ca.shared.global [%0], [%1], 8, %2;"
                 :: "r"(dst), "l"(src), "r"(srcsize));
}
__device__ __forceinline__ void cp_commit() {
    asm volatile("cp.async.commit_group;");
}
template <int N>
__device__ __forceinline__ void cp_wait() {
    asm volatile("cp.async.wait_group %0;" :: "n"(N));
}

// ---------------- twiddle table: exp(+2*pi*i*j/1024) -----------------------
__global__ void twiddle_kernel() {
    int j = threadIdx.x;
    if (j < 512) {
        float s, c;
        sincosf(6.283185307179586f * (float)j * (1.0f / 1024.0f), &s, &c);
        g_tw[j] = make_float2(c, s);
    }
}

// ---------------- Conv1d(512->1024,k=3,p=1) + GLU -> g_q2t[b,c,l] ----------
__global__ __launch_bounds__(256) void conv_glu_kernel(
        const float* __restrict__ q, const float* __restrict__ W,
        const float* __restrict__ bias) {
    __shared__ __align__(16) float pool[7200];
    float* sx  = pool;               // [16 ic][66 l]
    float* swa = pool + 1056;        // [48 r][64 oc]
    float* swg = pool + 1056 + 3072;

    int b   = blockIdx.x >> 4;
    int l0  = (blockIdx.x & 15) << 6;
    int oc0 = blockIdx.y << 6;
    int tid = threadIdx.x;
    int tx  = tid & 15, ty = tid >> 4;

    unsigned long long pa[4][2], pg[4][2];
#pragma unroll
    for (int i = 0; i < 4; i++) {
        pa[i][0] = pa[i][1] = 0ull;
        pg[i][0] = pg[i][1] = 0ull;
    }

    for (int ic0 = 0; ic0 < 512; ic0 += 16) {
        __syncthreads();
#pragma unroll
        for (int t = 0; t < 5; t++) {
            int idx = tid + (t << 8);
            if (idx < 1056) {
                int li = idx >> 4, kk = idx & 15;
                int l = l0 - 1 + li;
                float v = 0.0f;
                if ((unsigned)l < 1024u)
                    v = q[((size_t)b * 1024 + l) * 512 + ic0 + kk];
                sx[kk * 66 + li] = v;
            }
        }
#pragma unroll
        for (int t = 0; t < 12; t++) {
            int idx = tid + (t << 8);
            int oc = idx / 48, r = idx % 48;
            swa[r * 64 + oc] = W[(size_t)(oc0 + oc) * 1536 + ic0 * 3 + r];
        }
#pragma unroll
        for (int t = 0; t < 12; t++) {
            int idx = tid + (t << 8);
            int oc = idx / 48, r = idx % 48;
            swg[r * 64 + oc] = W[(size_t)(512 + oc0 + oc) * 1536 + ic0 * 3 + r];
        }
        __syncthreads();

#pragma unroll
        for (int kk = 0; kk < 16; kk++) {
            unsigned long long xm[4], x0[4], xp[4];
#pragma unroll
            for (int yl = 0; yl < 4; yl++) {
                int li = (ty << 2) + yl;
                float a  = sx[kk * 66 + li];
                float b2 = sx[kk * 66 + li + 1];
                float c2 = sx[kk * 66 + li + 2];
                xm[yl] = pk2(a, a); x0[yl] = pk2(b2, b2); xp[yl] = pk2(c2, c2);
            }
#pragma unroll
            for (int xl2 = 0; xl2 < 2; xl2++) {
                int oc = (tx << 2) + (xl2 << 1);
                unsigned long long wa0 = *(const unsigned long long*)(swa + (kk * 3 + 0) * 64 + oc);
                unsigned long long wa1 = *(const unsigned long long*)(swa + (kk * 3 + 1) * 64 + oc);
                unsigned long long wa2 = *(const unsigned long long*)(swa + (kk * 3 + 2) * 64 + oc);
                unsigned long long wg0 = *(const unsigned long long*)(swg + (kk * 3 + 0) * 64 + oc);
                unsigned long long wg1 = *(const unsigned long long*)(swg + (kk * 3 + 1) * 64 + oc);
                unsigned long long wg2 = *(const unsigned long long*)(swg + (kk * 3 + 2) * 64 + oc);
#pragma unroll
                for (int yl = 0; yl < 4; yl++) {
                    pa[yl][xl2] = ffma2(xm[yl], wa0, pa[yl][xl2]);
                    pa[yl][xl2] = ffma2(x0[yl], wa1, pa[yl][xl2]);
                    pa[yl][xl2] = ffma2(xp[yl], wa2, pa[yl][xl2]);
                    pg[yl][xl2] = ffma2(xm[yl], wg0, pg[yl][xl2]);
                    pg[yl][xl2] = ffma2(x0[yl], wg1, pg[yl][xl2]);
                    pg[yl][xl2] = ffma2(xp[yl], wg2, pg[yl][xl2]);
                }
            }
        }
    }

    __syncthreads();
    float* st = pool;                // [64 oc][65 l]
#pragma unroll
    for (int yl = 0; yl < 4; yl++) {
#pragma unroll
        for (int xl2 = 0; xl2 < 2; xl2++) {
            float a0, a1, g0, g1;
            upk2(pa[yl][xl2], a0, a1);
            upk2(pg[yl][xl2], g0, g1);
            int oc = (tx << 2) + (xl2 << 1);
            a0 += bias[oc0 + oc];       a1 += bias[oc0 + oc + 1];
            g0 += bias[512 + oc0 + oc]; g1 += bias[512 + oc0 + oc + 1];
            int li = (ty << 2) + yl;
            st[oc * 65 + li]       = a0 * sigmoidf_(g0);
            st[(oc + 1) * 65 + li] = a1 * sigmoidf_(g1);
        }
    }
    __syncthreads();
#pragma unroll
    for (int t = 0; t < 16; t++) {
        int idx = tid + (t << 8);
        int c = idx >> 6, li = idx & 63;
        g_q2t[((size_t)b * 512 + oc0 + c) * 1024 + l0 + li] = st[c * 65 + li];
    }
}

// ---------------- 1024-pt radix-2 Stockham (DIF, natural order) ------------
__device__ __forceinline__ void fft1024_shared(float2* bufA, float2* bufB,
                                               float sgn, int tid) {
    float2* src = bufA;
    float2* dst = bufB;
    int m = 1;
#pragma unroll
    for (int stage = 0; stage < 10; stage++) {
#pragma unroll
        for (int u = 0; u < 2; u++) {
            int idx = tid + (u << 8);
            float2 c0 = src[idx];
            float2 c1 = src[idx + 512];
            int k = idx & (m - 1);
            int o = idx + (idx - k);
            float2 w = g_tw[idx - k];
            float wy = w.y * sgn;
            float trx = c0.x - c1.x, trY = c0.y - c1.y;
            dst[o]     = make_float2(c0.x + c1.x, c0.y + c1.y);
            dst[o + m] = make_float2(w.x * trx - wy * trY, w.x * trY + wy * trx);
        }
        __syncthreads();
        float2* t = src; src = dst; dst = t;
        m <<= 1;
    }
}

// rfft of q (conv output, contiguous rows) -> transposed [bh][x][e]
__global__ __launch_bounds__(256) void rfft_q_kernel() {
    __shared__ float2 bufA[1024];
    __shared__ float2 bufB[1024];
    int row = blockIdx.x, tid = threadIdx.x;
    const float* p = g_q2t + (size_t)row * 1024;
    for (int i = tid; i < 1024; i += 256) bufA[i] = make_float2(p[i], 0.0f);
    __syncthreads();
    fft1024_shared(bufA, bufB, -1.0f, tid);
    int bh = row >> 6, e = row & 63;
    size_t ob = (size_t)bh * LF * 64 + e;
    for (int i = tid; i < 513; i += 256) {
        float2 vv = bufA[i];
        g_qft_re[ob + (size_t)i * 64] = vv.x * 0.03125f;
        g_qft_im[ob + (size_t)i * 64] = vv.y * 0.03125f;
    }
}

// rfft of k (-> transposed) and v (-> padded [row][514]) in one launch
__global__ __launch_bounds__(256) void rfft_kv_kernel(const float* __restrict__ kin,
                                                      const float* __restrict__ vin) {
    __shared__ float2 bufA[1024];
    __shared__ float2 bufB[1024];
    int row = blockIdx.x, tid = threadIdx.x;
    int isv = blockIdx.y;
    const float* in = isv ? vin : kin;
    const float* p = in + (size_t)(row >> 9) * 524288 + (row & 511);
    for (int i = tid; i < 1024; i += 256)
        bufA[i] = make_float2(p[(size_t)i * 512], 0.0f);
    __syncthreads();
    fft1024_shared(bufA, bufB, -1.0f, tid);
    if (isv) {
        size_t ob = (size_t)row * VPITCH;
        for (int i = tid; i < 513; i += 256) {
            float2 vv = bufA[i];
            g_vf_re[ob + i] = vv.x * 0.03125f;
            g_vf_im[ob + i] = vv.y * 0.03125f;
        }
    } else {
        int bh = row >> 6, e = row & 63;
        size_t ob = (size_t)bh * LF * 64 + e;
        for (int i = tid; i < 513; i += 256) {
            float2 vv = bufA[i];
            g_kft_re[ob + (size_t)i * 64] = vv.x * 0.03125f;
            g_kft_im[ob + (size_t)i * 64] = vv.y * 0.03125f;
        }
    }
}

// ---------------- fused frequency attention: f32x2 + cp.async pipeline -----
__global__ __launch_bounds__(256) void attn_kernel() {
    extern __shared__ float sm[];
    float* Qre = sm;                  // [x][e] pitch 66
    float* Qim = sm + 4224;
    float* Kre = sm + 8448;           // [y][e] pitch 66
    float* Kim = sm + 12672;
    float* Vre = sm + 16896;          // [e][y] pitch 66
    float* Vim = sm + 21120;
    float* Tre = sm + 25344;          // [x][y] pitch 66
    float* Tim = sm + 29568;

    int bh  = blockIdx.y;
    int x0  = blockIdx.x << 6;
    int tid = threadIdx.x;
    int tx  = tid & 15, ty = tid >> 4;
    size_t tbase = (size_t)bh * LF * 64;    // transposed spectra base
    size_t obase = (size_t)bh * 64 * LF;    // of output base

    unsigned int sQre = (unsigned int)__cvta_generic_to_shared(Qre);
    unsigned int sQim = (unsigned int)__cvta_generic_to_shared(Qim);
    unsigned int sKre = (unsigned int)__cvta_generic_to_shared(Kre);
    unsigned int sKim = (unsigned int)__cvta_generic_to_shared(Kim);
    unsigned int sVre = (unsigned int)__cvta_generic_to_shared(Vre);
    unsigned int sVim = (unsigned int)__cvta_generic_to_shared(Vim);

    // ---- issue Q tile + K tile 0 (group 1), V tile 0 (group 2) ----
    {
        // Q: rows x0+r (r=flat>>5), e-pair p=flat&31
#pragma unroll
        for (int o = 0; o < 8; o++) {
            int flat = tid + (o << 8);
            int r = flat >> 5, p = flat & 31;
            int valid = (x0 + r) < 513;
            const float* sre = g_qft_re + tbase + (size_t)(x0 + r) * 64 + 2 * p;
            const float* sim = g_qft_im + tbase + (size_t)(x0 + r) * 64 + 2 * p;
            unsigned int d = (unsigned int)((r * 66 + 2 * p) * 4);
            cp8(sQre + d, valid ? sre : g_qft_re, valid ? 8 : 0);
            cp8(sQim + d, valid ? sim : g_qft_im, valid ? 8 : 0);
        }
#pragma unroll
        for (int o = 0; o < 8; o++) {
            int flat = tid + (o << 8);
            int r = flat >> 5, p = flat & 31;
            const float* sre = g_kft_re + tbase + (size_t)r * 64 + 2 * p;
            const float* sim = g_kft_im + tbase + (size_t)r * 64 + 2 * p;
            unsigned int d = (unsigned int)((r * 66 + 2 * p) * 4);
            cp8(sKre + d, sre, 8);
            cp8(sKim + d, sim, 8);
        }
        cp_commit();
#pragma unroll
        for (int o = 0; o < 8; o++) {
            int flat = tid + (o << 8);
            int r = flat >> 5, p = flat & 31;
            const float* sre = g_vf_re + (size_t)(bh * 64 + r) * VPITCH + 2 * p;
            const float* sim = g_vf_im + (size_t)(bh * 64 + r) * VPITCH + 2 * p;
            unsigned int d = (unsigned int)((r * 66 + 2 * p) * 4);
            cp8(sVre + d, sre, 8);
            cp8(sVim + d, sim, 8);
        }
        cp_commit();
    }

    int qb[4], kb[4];
#pragma unroll
    for (int i = 0; i < 4; i++) qb[i] = rowbase((ty << 2) + i);
#pragma unroll
    for (int j = 0; j < 4; j++) kb[j] = rowbase(tx + (j << 4));

    unsigned long long ore_p[4][4], oim_p[4][4];
#pragma unroll
    for (int i = 0; i < 4; i++)
#pragma unroll
        for (int j = 0; j < 4; j++) { ore_p[i][j] = 0ull; oim_p[i][j] = 0ull; }
    float Dacc[4] = {};

    cp_wait<1>();          // Q + K0 ready
    __syncthreads();

    for (int yt = 0; yt < 9; yt++) {
        // ---- GEMM1: s[x,y] = sum_e qf*conj(kf) ----
        unsigned long long sre_p[4][4], sim_p[4][4];
#pragma unroll
        for (int i = 0; i < 4; i++)
#pragma unroll
            for (int j = 0; j < 4; j++) { sre_p[i][j] = 0ull; sim_p[i][j] = 0ull; }

        for (int e2 = 0; e2 < 32; e2++) {
            unsigned long long qr[4], qi[4], qrn[4], kr[4], ki[4];
            int off = e2 << 1;
#pragma unroll
            for (int i = 0; i < 4; i++) {
                qr[i] = *(const unsigned long long*)(Qre + qb[i] + off);
                qi[i] = *(const unsigned long long*)(Qim + qb[i] + off);
                qrn[i] = neg2(qr[i]);
            }
#pragma unroll
            for (int j = 0; j < 4; j++) {
                kr[j] = *(const unsigned long long*)(Kre + kb[j] + off);
                ki[j] = *(const unsigned long long*)(Kim + kb[j] + off);
            }
#pragma unroll
            for (int i = 0; i < 4; i++)
#pragma unroll
                for (int j = 0; j < 4; j++) {
                    sre_p[i][j] = ffma2(qr[i],  kr[j], sre_p[i][j]);
                    sre_p[i][j] = ffma2(qi[i],  ki[j], sre_p[i][j]);
                    sim_p[i][j] = ffma2(qi[i],  kr[j], sim_p[i][j]);
                    sim_p[i][j] = ffma2(qrn[i], ki[j], sim_p[i][j]);
                }
        }
        __syncthreads();      // all K reads done

        // ---- prefetch K_{t+1} (completes under epilogue + GEMM2) ----
        if (yt < 8) {
            int y0n = (yt + 1) << 6;
#pragma unroll
            for (int o = 0; o < 8; o++) {
                int flat = tid + (o << 8);
                int r = flat >> 5, p = flat & 31;
                int valid = (y0n + r) < 513;
                const float* sre = g_kft_re + tbase + (size_t)(y0n + r) * 64 + 2 * p;
                const float* sim = g_kft_im + tbase + (size_t)(y0n + r) * 64 + 2 * p;
                unsigned int d = (unsigned int)((r * 66 + 2 * p) * 4);
                cp8(sKre + d, valid ? sre : g_kft_re, valid ? 8 : 0);
                cp8(sKim + d, valid ? sim : g_kft_im, valid ? 8 : 0);
            }
            cp_commit();
        }

        // ---- gating epilogue -> T[x][y] + D partials ----
#pragma unroll
        for (int i = 0; i < 4; i++)
#pragma unroll
            for (int j = 0; j < 4; j++) {
                float a0, a1, b0, b1;
                upk2(sre_p[i][j], a0, a1);
                upk2(sim_p[i][j], b0, b1);
                float sr = (a0 + a1) * 0.125f;
                float si = (b0 + b1) * 0.125f;
                float mg = sqrtf(sr * sr + si * si);
                float w  = 1.0f + sigmoidf_(mg);
                Dacc[i] += mg * w;
                int a = qb[i] + tx + (j << 4);
                Tre[a] = sr * w;
                Tim[a] = si * w;
            }

        if (yt < 8) cp_wait<1>(); else cp_wait<0>();
        __syncthreads();      // V_t ready, T visible

        // ---- GEMM2: of[x,e] += sum_y T[x,y]*V[e,y] ----
        for (int y2 = 0; y2 < 32; y2++) {
            unsigned long long tr[4], ti[4], tin[4], vr[4], vi[4];
            int off = y2 << 1;
#pragma unroll
            for (int i = 0; i < 4; i++) {
                tr[i] = *(const unsigned long long*)(Tre + qb[i] + off);
                ti[i] = *(const unsigned long long*)(Tim + qb[i] + off);
                tin[i] = neg2(ti[i]);
            }
#pragma unroll
            for (int j = 0; j < 4; j++) {
                vr[j] = *(const unsigned long long*)(Vre + kb[j] + off);
                vi[j] = *(const unsigned long long*)(Vim + kb[j] + off);
            }
#pragma unroll
            for (int i = 0; i < 4; i++)
#pragma unroll
                for (int j = 0; j < 4; j++) {
                    ore_p[i][j] = ffma2(tr[i],  vr[j], ore_p[i][j]);
                    ore_p[i][j] = ffma2(tin[i], vi[j], ore_p[i][j]);
                    oim_p[i][j] = ffma2(tr[i],  vi[j], oim_p[i][j]);
                    oim_p[i][j] = ffma2(ti[i],  vr[j], oim_p[i][j]);
                }
        }
        __syncthreads();      // all V/T reads done

        // ---- prefetch V_{t+1}, then wait for K_{t+1} ----
        if (yt < 8) {
            int y0n = (yt + 1) << 6;
#pragma unroll
            for (int o = 0; o < 8; o++) {
                int flat = tid + (o << 8);
                int r = flat >> 5, p = flat & 31;
                int rem = 513 - (y0n + 2 * p);
                int sz = rem >= 2 ? 8 : (rem == 1 ? 4 : 0);
                const float* sre = g_vf_re + (size_t)(bh * 64 + r) * VPITCH + y0n + 2 * p;
                const float* sim = g_vf_im + (size_t)(bh * 64 + r) * VPITCH + y0n + 2 * p;
                unsigned int d = (unsigned int)((r * 66 + 2 * p) * 4);
                cp8(sVre + d, sre, sz);
                cp8(sVim + d, sim, sz);
            }
            cp_commit();
            cp_wait<1>();     // K_{t+1} ready
            __syncthreads();
        }
    }

    // reduce D over tx lanes (bits 0..3)
#pragma unroll
    for (int i = 0; i < 4; i++) {
        float dsum = Dacc[i];
        dsum += __shfl_xor_sync(0xffffffffu, dsum, 1);
        dsum += __shfl_xor_sync(0xffffffffu, dsum, 2);
        dsum += __shfl_xor_sync(0xffffffffu, dsum, 4);
        dsum += __shfl_xor_sync(0xffffffffu, dsum, 8);
        Dacc[i] = 1.0f / fmaxf(dsum, 1e-12f);
    }
#pragma unroll
    for (int i = 0; i < 4; i++) {
        int x = x0 + (ty << 2) + i;
        if (x < 513) {
#pragma unroll
            for (int j = 0; j < 4; j++) {
                int e = tx + (j << 4);
                float a0, a1, b0, b1;
                upk2(ore_p[i][j], a0, a1);
                upk2(oim_p[i][j], b0, b1);
                g_of_re[obase + (size_t)e * 513 + x] = (a0 + a1) * Dacc[i];
                g_of_im[obase + (size_t)e * 513 + x] = (b0 + b1) * Dacc[i];
            }
        }
    }
}

// ---------------- irfft (ortho) + scatter to out[b,l,h,e] ------------------
__global__ __launch_bounds__(256) void irfft_kernel(float* __restrict__ out) {
    __shared__ float2 bufA[1024];
    __shared__ float2 bufB[1024];
    int row = blockIdx.x, tid = threadIdx.x;
    const float* pr = g_of_re + (size_t)row * 513;
    const float* pi = g_of_im + (size_t)row * 513;
    for (int i = tid; i < 1024; i += 256) {
        float re, im;
        if (i < 513) { re = pr[i];        im =  pi[i]; }
        else         { re = pr[1024 - i]; im = -pi[1024 - i]; }
        bufA[i] = make_float2(re, im);
    }
    __syncthreads();
    fft1024_shared(bufA, bufB, 1.0f, tid);
    int b = row >> 9, c = row & 511;
    float* po = out + (size_t)b * 524288 + c;
    for (int i = tid; i < 1024; i += 256)
        po[(size_t)i * 512] = bufA[i].x * 0.03125f;
}

// ---------------- launch ---------------------------------------------------
extern "C" void kernel_launch(void* const* d_in, const int* in_sizes, int n_in,
                              void* d_out, int out_size) {
    const float* q    = (const float*)d_in[0];
    const float* k    = (const float*)d_in[1];
    const float* v    = (const float*)d_in[2];
    const float* W    = (const float*)d_in[3];
    const float* bias = (const float*)d_in[4];
    float* out = (float*)d_out;

    const int attn_smem = 33792 * (int)sizeof(float);   // 135168 B
    cudaFuncSetAttribute(attn_kernel,
                         cudaFuncAttributeMaxDynamicSharedMemorySize, attn_smem);

    twiddle_kernel<<<1, 512>>>();
    conv_glu_kernel<<<dim3(256, 8), 256>>>(q, W, bias);
    rfft_q_kernel<<<NROW, 256>>>();
    rfft_kv_kernel<<<dim3(NROW, 2), 256>>>(k, v);
    attn_kernel<<<dim3(9, 128), 256, attn_smem>>>();
    irfft_kernel<<<NROW, 256>>>(out);
}